// round 5
// baseline (speedup 1.0000x reference)
#include <cuda_runtime.h>
#include <cuda_bf16.h>
#include <cstdint>

#define BDIM 8192
#define HDIM 512
#define NG   2048           // 4*H gate-interleaved output cols
#define NSTAGE 16           // K stages of 64 (B-K = 1024)
#define NBUF 3
#define A_TILE 32768        // per (rb128,kb): hi 16KB + lo 16KB, pre-swizzled
#define B_TILE 32768        // per (cb,rank,kb): 256 rows x 128B, pre-swizzled
#define STAGE_BYTES (A_TILE + B_TILE)          // 64 KB
#define SMEM_TOTAL (1024 + NBUF * STAGE_BYTES) // 197632
#define IDESC_CG2 0x10400490u   // f32 accum, bf16 x bf16, M=256, N=256

#if !defined(__CUDA_ARCH__) || defined(__CUDA_ARCH_FEAT_SM103_ALL) || defined(__CUDA_ARCH_FEAT_SM100_ALL)
#define TCGEN05_OK 1
#else
#define TCGEN05_OK 0
#endif

// scratch (device globals — allocation-free rule). Tiled + pre-swizzled.
__device__ __align__(1024) unsigned char g_Atile[(size_t)64 * 16 * A_TILE];  // 32 MB
__device__ __align__(1024) unsigned char g_Btile[(size_t)8 * 16 * B_TILE];   // 4 MB
__device__ __align__(16) float g_bias[NG];

// ---------------- PTX helpers -------------------------------------------------------
__device__ __forceinline__ uint32_t smem_u32(const void* p) {
    return (uint32_t)__cvta_generic_to_shared(p);
}
__device__ __forceinline__ void mbar_init(uint32_t a, uint32_t cnt) {
    asm volatile("mbarrier.init.shared.b64 [%0], %1;" :: "r"(a), "r"(cnt) : "memory");
}
__device__ __forceinline__ void mbar_wait(uint32_t a, uint32_t parity) {
    uint32_t done;
    asm volatile("{\n\t.reg .pred p;\n\t"
                 "mbarrier.try_wait.parity.acquire.cta.shared::cta.b64 p, [%1], %2;\n\t"
                 "selp.b32 %0, 1, 0, p;\n\t}"
                 : "=r"(done) : "r"(a), "r"(parity) : "memory");
    if (!done) {
        asm volatile("{\n\t.reg .pred P1;\n\t"
                     "W_%=:\n\t"
                     "mbarrier.try_wait.parity.acquire.cta.shared::cta.b64 P1, [%0], %1, 0x989680;\n\t"
                     "@P1 bra.uni D_%=;\n\t"
                     "bra.uni W_%=;\n\t"
                     "D_%=:\n\t}" :: "r"(a), "r"(parity) : "memory");
    }
}
__device__ __forceinline__ void mbar_expect_tx(uint32_t a, uint32_t bytes) {
    asm volatile("mbarrier.arrive.expect_tx.shared.b64 _, [%0], %1;"
                 :: "r"(a), "r"(bytes) : "memory");
}
__device__ __forceinline__ void mbar_arrive_cluster(uint32_t local_addr, uint32_t rank) {
    asm volatile("{\n\t.reg .b32 remAddr32;\n\t"
                 "mapa.shared::cluster.u32 remAddr32, %0, %1;\n\t"
                 "mbarrier.arrive.shared::cluster.b64 _, [remAddr32];\n\t}"
                 :: "r"(local_addr), "r"(rank) : "memory");
}
__device__ __forceinline__ void bulk_g2s(uint32_t dst, const void* src, uint32_t bytes,
                                         uint32_t mbar) {
    asm volatile("cp.async.bulk.shared::cta.global.mbarrier::complete_tx::bytes "
                 "[%0], [%1], %2, [%3];"
                 :: "r"(dst), "l"(src), "r"(bytes), "r"(mbar) : "memory");
}
__device__ __forceinline__ uint64_t mk_desc(uint32_t addr) {
    // SW128, Blackwell version=1, SBO=64, LBO=1
    const uint64_t base = (uint64_t(2) << 61) | (uint64_t(1) << 46) |
                          (uint64_t(64) << 32) | (uint64_t(1) << 16);
    return base | ((uint64_t)(addr >> 4) & 0x3FFF);
}
__device__ __forceinline__ void cluster_sync() {
    asm volatile("barrier.cluster.arrive.aligned;" ::: "memory");
    asm volatile("barrier.cluster.wait.aligned;" ::: "memory");
}
#if TCGEN05_OK
__device__ __forceinline__ void mma_f16_cg2(uint32_t d, uint64_t ad, uint64_t bd,
                                            uint32_t en) {
    asm volatile("{\n\t.reg .pred p;\n\tsetp.ne.u32 p, %4, 0;\n\t"
                 "tcgen05.mma.cta_group::2.kind::f16 [%0], %1, %2, %3, "
                 "{%5,%5,%5,%5,%5,%5,%5,%5}, p;\n\t}"
                 :: "r"(d), "l"(ad), "l"(bd), "r"(IDESC_CG2), "r"(en), "r"(0u) : "memory");
}
__device__ __forceinline__ void tc_commit_mc2(uint32_t mbar) {
    asm volatile("tcgen05.commit.cta_group::2.mbarrier::arrive::one.shared::cluster"
                 ".multicast::cluster.b64 [%0], %1;"
                 :: "r"(mbar), "h"((uint16_t)0x3) : "memory");
}
#define TC_LD_X32(r, addr)                                                     \
    asm volatile("tcgen05.ld.sync.aligned.32x32b.x32.b32 "                     \
        "{%0,%1,%2,%3,%4,%5,%6,%7,%8,%9,%10,%11,%12,%13,%14,%15,"             \
        "%16,%17,%18,%19,%20,%21,%22,%23,%24,%25,%26,%27,%28,%29,%30,%31}, [%32];" \
        : "=r"((r)[0]),"=r"((r)[1]),"=r"((r)[2]),"=r"((r)[3]),                 \
          "=r"((r)[4]),"=r"((r)[5]),"=r"((r)[6]),"=r"((r)[7]),                 \
          "=r"((r)[8]),"=r"((r)[9]),"=r"((r)[10]),"=r"((r)[11]),               \
          "=r"((r)[12]),"=r"((r)[13]),"=r"((r)[14]),"=r"((r)[15]),             \
          "=r"((r)[16]),"=r"((r)[17]),"=r"((r)[18]),"=r"((r)[19]),             \
          "=r"((r)[20]),"=r"((r)[21]),"=r"((r)[22]),"=r"((r)[23]),             \
          "=r"((r)[24]),"=r"((r)[25]),"=r"((r)[26]),"=r"((r)[27]),             \
          "=r"((r)[28]),"=r"((r)[29]),"=r"((r)[30]),"=r"((r)[31])              \
        : "r"(addr))
#endif

// ---------------- prep: weights -> g_Btile ------------------------------------------
// Output col n: cb=n>>9, half=(n>>7)&1 (owning CTA rank), B-row=((n>>8)&1)*128+(n&127).
// TMEM col within tile == n&511 (identity mapping by construction).
__global__ void prep_w(const float* __restrict__ Wih, const float* __restrict__ Whh,
                       const float* __restrict__ bih, const float* __restrict__ bhh) {
    int idx = blockIdx.x * blockDim.x + threadIdx.x;    // NG * 128
    if (idx >= NG * 128) return;
    int n = idx >> 7, k4 = (idx & 127) * 4;
    int row_w = (n & 3) * HDIM + (n >> 2);              // source weight row
    int cb = n >> 9;
    int half = (n >> 7) & 1;
    int brow = ((n >> 8) & 1) * 128 + (n & 127);
    int kb = k4 >> 6, col = k4 & 63;
    float4 wi = *(const float4*)(Wih + (size_t)row_w * 512 + k4);
    float4 wh = *(const float4*)(Whh + (size_t)row_w * 512 + k4);
    __nv_bfloat16 si[4], sh[4];
    const float* pi = &wi.x; const float* ph = &wh.x;
#pragma unroll
    for (int j = 0; j < 4; j++) {
        si[j] = __float2bfloat16(pi[j] > 0.f ? 1.f : (pi[j] < 0.f ? -1.f : 0.f));
        sh[j] = __float2bfloat16(ph[j] > 0.f ? 1.f : (ph[j] < 0.f ? -1.f : 0.f));
    }
    uint32_t inner = (uint32_t)(brow * 128 + col * 2);
    uint32_t sw = inner ^ ((inner >> 3) & 0x70);
    unsigned char* base = g_Btile + ((size_t)(cb * 2 + half) * 16) * B_TILE;
    *(uint2*)(base + (size_t)kb * B_TILE + sw)       = *(uint2*)si;  // K [0,512)
    *(uint2*)(base + (size_t)(8 + kb) * B_TILE + sw) = *(uint2*)sh;  // K [512,1024)
    if (k4 == 0) g_bias[n] = bih[row_w] + bhh[row_w];
}

// ---------------- prep: activations -> g_Atile (hi/lo bf16 split, swizzled) ----------
__global__ void prep_a(const float* __restrict__ x, const float* __restrict__ hx) {
    int idx = blockIdx.x * blockDim.x + threadIdx.x;    // BDIM * 128
    if (idx >= BDIM * 128) return;
    int b = idx >> 7, k4 = (idx & 127) * 4;
    int rb = b >> 7, row = b & 127;
    int kb = k4 >> 6, col = k4 & 63;
    float4 vx = *(const float4*)(x + (size_t)b * 512 + k4);
    float4 vh = *(const float4*)(hx + (size_t)b * 512 + k4);
    __nv_bfloat16 xh[4], xl[4], hh[4], hl[4];
    const float* px = &vx.x; const float* pv = &vh.x;
#pragma unroll
    for (int j = 0; j < 4; j++) {
        xh[j] = __float2bfloat16(px[j]);
        xl[j] = __float2bfloat16(px[j] - __bfloat162float(xh[j]));
        hh[j] = __float2bfloat16(pv[j]);
        hl[j] = __float2bfloat16(pv[j] - __bfloat162float(hh[j]));
    }
    uint32_t inner = (uint32_t)(row * 128 + col * 2);
    uint32_t sw = inner ^ ((inner >> 3) & 0x70);
    unsigned char* base = g_Atile + (size_t)rb * 16 * A_TILE;
    *(uint2*)(base + (size_t)kb * A_TILE + sw)               = *(uint2*)xh;
    *(uint2*)(base + (size_t)kb * A_TILE + 16384 + sw)       = *(uint2*)xl;
    *(uint2*)(base + (size_t)(8 + kb) * A_TILE + sw)         = *(uint2*)hh;
    *(uint2*)(base + (size_t)(8 + kb) * A_TILE + 16384 + sw) = *(uint2*)hl;
}

// ---------------- cg2 tcgen05 GEMM + fused LSTM epilogue ----------------------------
// Cluster pair computes M=256 x N=512. Per CTA per stage: A 32KB + B-half 32KB.
// Depth-3 pipeline; tid32 = load issuer, tid64 = ready-relay, leader tid0 = MMA.
__global__ void __launch_bounds__(256, 1) __cluster_dims__(2, 1, 1)
blstm_gemm(const float* __restrict__ cx, float* __restrict__ out) {
#if TCGEN05_OK
    extern __shared__ __align__(1024) unsigned char smem[];
    const int tid = threadIdx.x;
    const int lane = tid & 31, warp = tid >> 5;
    const int bx = blockIdx.x, cb = blockIdx.y;
    const uint32_t rank = bx & 1;                       // == cluster_ctarank
    const uint32_t sbase = smem_u32(smem);
    const uint32_t ldmbar[NBUF]  = {sbase + 16, sbase + 24, sbase + 32};
    const uint32_t rdymbar[NBUF] = {sbase + 40, sbase + 48, sbase + 56};
    const uint32_t mmambar[NBUF] = {sbase + 64, sbase + 72, sbase + 80};
    const uint32_t finmbar       = sbase + 88;

    if (tid == 0) {
#pragma unroll
        for (int i = 0; i < NBUF; i++) {
            mbar_init(ldmbar[i], 1);
            mbar_init(rdymbar[i], 2);                   // both CTAs' relays arrive
            mbar_init(mmambar[i], 1);                   // multicast commit arrives
        }
        mbar_init(finmbar, 1);
    }
    if (warp == 0) {
        asm volatile("tcgen05.alloc.cta_group::2.sync.aligned.shared::cta.b32 [%0], %1;"
                     :: "r"(sbase), "r"(512u) : "memory");
    }
    __syncthreads();
    cluster_sync();                                      // peer mbars initialized
    uint32_t tmem;
    asm volatile("ld.shared.b32 %0, [%1];" : "=r"(tmem) : "r"(sbase));

    const unsigned char* Asrc0 = g_Atile + (size_t)bx * 16 * A_TILE;
    const unsigned char* Bsrc0 = g_Btile + ((size_t)(cb * 2 + (int)rank) * 16) * B_TILE;

    if (tid == 32) {
        // ---- load issuer (both CTAs) ----
        int mph[NBUF] = {0, 0, 0};
#pragma unroll 1
        for (int s = 0; s < NSTAGE; s++) {
            int buf = s % NBUF;
            if (s >= NBUF) {                            // buffer freed by MMA(s-3)
                mbar_wait(mmambar[buf], (uint32_t)mph[buf]);
                mph[buf] ^= 1;
            }
            uint32_t st = sbase + 1024 + (uint32_t)buf * STAGE_BYTES;
            mbar_expect_tx(ldmbar[buf], STAGE_BYTES);
            bulk_g2s(st,          Asrc0 + (size_t)s * A_TILE, A_TILE, ldmbar[buf]);
            bulk_g2s(st + A_TILE, Bsrc0 + (size_t)s * B_TILE, B_TILE, ldmbar[buf]);
        }
    } else if (tid == 64) {
        // ---- ready relay (both CTAs): own load done -> leader's rdymbar ----
        int lph[NBUF] = {0, 0, 0};
#pragma unroll 1
        for (int s = 0; s < NSTAGE; s++) {
            int buf = s % NBUF;
            mbar_wait(ldmbar[buf], (uint32_t)lph[buf]);
            lph[buf] ^= 1;
            mbar_arrive_cluster(rdymbar[buf], 0);
        }
    } else if (tid == 0 && rank == 0) {
        // ---- MMA issuer (leader only) ----
        int rph[NBUF] = {0, 0, 0};
#pragma unroll 1
        for (int s = 0; s < NSTAGE; s++) {
            int buf = s % NBUF;
            mbar_wait(rdymbar[buf], (uint32_t)rph[buf]);
            rph[buf] ^= 1;
            uint32_t st = sbase + 1024 + (uint32_t)buf * STAGE_BYTES;
            uint64_t ah = mk_desc(st);                  // A hi
            uint64_t al = mk_desc(st + 16384);          // A lo
            uint64_t b0 = mk_desc(st + A_TILE);         // B rows [0,128) per CTA
            uint64_t b1 = b0 + 1024;                    // B rows [128,256) per CTA
#pragma unroll
            for (int k = 0; k < 4; k++) {
                uint32_t en = (s == 0 && k == 0) ? 0u : 1u;
                mma_f16_cg2(tmem,       ah + 2 * k, b0 + 2 * k, en);
                mma_f16_cg2(tmem + 256, ah + 2 * k, b1 + 2 * k, en);
            }
#pragma unroll
            for (int k = 0; k < 4; k++) {
                mma_f16_cg2(tmem,       al + 2 * k, b0 + 2 * k, 1u);
                mma_f16_cg2(tmem + 256, al + 2 * k, b1 + 2 * k, 1u);
            }
            tc_commit_mc2(mmambar[buf]);
            if (s == NSTAGE - 1) tc_commit_mc2(finmbar);
        }
    }

    // ---- all threads: final MMA completion (single-phase) ----
    mbar_wait(finmbar, 0u);
    asm volatile("tcgen05.fence::after_thread_sync;" ::: "memory");

    // ---- register-direct LSTM epilogue (each CTA owns 128 D rows in its TMEM) ----
    const int half = warp >> 2;            // warpgroup: col half of 64-chunk
    const int sp   = warp & 3;             // TMEM subpartition
    const int row  = sp * 32 + lane;
    const int grow = bx * 128 + row;       // = rbp*256 + rank*128 + row
#pragma unroll 1
    for (int ch = 0; ch < 8; ch++) {
        uint32_t r[32];
        TC_LD_X32(r, tmem + ch * 64 + half * 32);
        asm volatile("tcgen05.wait::ld.sync.aligned;" ::: "memory");
        int gu = cb * 128 + ch * 16 + half * 8;         // first of 8 hidden units
        float4 cx0 = *(const float4*)(cx + (size_t)grow * HDIM + gu);
        float4 cx1 = *(const float4*)(cx + (size_t)grow * HDIM + gu + 4);
        float cprev[8] = {cx0.x, cx0.y, cx0.z, cx0.w, cx1.x, cx1.y, cx1.z, cx1.w};
        const float4* bias4 = (const float4*)&g_bias[cb * 512 + ch * 64 + half * 32];
        float hy[8], cy[8];
#pragma unroll
        for (int j = 0; j < 8; j++) {
            float4 bs = bias4[j];
            float ig = __uint_as_float(r[j * 4 + 0]) + bs.x;
            float fg = __uint_as_float(r[j * 4 + 1]) + bs.y;
            float cg = __uint_as_float(r[j * 4 + 2]) + bs.z;
            float og = __uint_as_float(r[j * 4 + 3]) + bs.w;
            float si = 1.f / (1.f + __expf(-ig));
            float sf = 1.f / (1.f + __expf(-fg));
            float so = 1.f / (1.f + __expf(-og));
            float tc = 2.f / (1.f + __expf(-2.f * cg)) - 1.f;
            float c = sf * cprev[j] + si * tc;
            cy[j] = c;
            hy[j] = so * (2.f / (1.f + __expf(-2.f * c)) - 1.f);
        }
        float* oh = out + (size_t)grow * HDIM + gu;
        float* oc = out + (size_t)BDIM * HDIM + (size_t)grow * HDIM + gu;
        *(float4*)oh       = make_float4(hy[0], hy[1], hy[2], hy[3]);
        *(float4*)(oh + 4) = make_float4(hy[4], hy[5], hy[6], hy[7]);
        *(float4*)oc       = make_float4(cy[0], cy[1], cy[2], cy[3]);
        *(float4*)(oc + 4) = make_float4(cy[4], cy[5], cy[6], cy[7]);
    }

    __syncthreads();
    cluster_sync();                                      // pair done before dealloc
    if (warp == 0) {
        asm volatile("tcgen05.relinquish_alloc_permit.cta_group::2.sync.aligned;");
        asm volatile("tcgen05.dealloc.cta_group::2.sync.aligned.b32 %0, %1;"
                     :: "r"(tmem), "r"(512u));
    }
#endif  // TCGEN05_OK
}

// ---------------- launch ------------------------------------------------------------
extern "C" void kernel_launch(void* const* d_in, const int* in_sizes, int n_in,
                              void* d_out, int out_size) {
    const float* x   = (const float*)d_in[0];
    const float* hx  = (const float*)d_in[1];
    const float* cx  = (const float*)d_in[2];
    const float* Wih = (const float*)d_in[3];
    const float* Whh = (const float*)d_in[4];
    const float* bih = (const float*)d_in[5];
    const float* bhh = (const float*)d_in[6];
    float* out = (float*)d_out;

    cudaFuncSetAttribute(blstm_gemm, cudaFuncAttributeMaxDynamicSharedMemorySize,
                         SMEM_TOTAL);
    prep_w<<<(NG * 128 + 255) / 256, 256>>>(Wih, Whh, bih, bhh);
    prep_a<<<(BDIM * 128 + 255) / 256, 256>>>(x, hx);
    dim3 grid(BDIM / 128, NG / 512);      // 64 x 4 CTAs = 32x4 cluster pairs
    blstm_gemm<<<grid, 256, SMEM_TOTAL>>>(cx, out);
}